// round 11
// baseline (speedup 1.0000x reference)
#include <cuda_runtime.h>
#include <math.h>

#define FM_C 256
#define FM_H 200
#define FM_W 200
#define IIH 201
#define IIW 201
#define NBOX 1024
#define OH 7
#define OW 7
#define NBINS 49

// Integral image scratch, channel-last layout: [y][x][c], y,x in 0..200.
// After k1: ii[y+1][x+1][c] = x-cumsum of fm row y. After k2: full 2D cumsum.
__device__ float g_ii[IIH * IIW * FM_C];      // 41.4 MB

// ---------------------------------------------------------------------------
// K1: x-cumsum fused with transpose [C][H][W] -> [y+1][x+1][C].
// Grid (8 c-tiles, 200 rows), 512 threads (16 warps); each warp owns TWO
// channels (4-way scan ILP), 4 blocks/SM. float4 loads, quad-prefix + warp
// scans, float4 STS into XOR-swizzled [c][256] staging, float4 STG.
// ---------------------------------------------------------------------------
__global__ void __launch_bounds__(512) k1_xcum_transpose(const float* __restrict__ fm) {
    __shared__ float sh[32 * 256];         // 32 KB
    const int w2 = threadIdx.x >> 5;       // warp 0..15 -> channels 2w2, 2w2+1
    const int l = threadIdx.x & 31;
    const int c0 = blockIdx.x * 32;
    const int y  = blockIdx.y;             // fm row 0..199
    const int cA = 2 * w2;
    const int cB = 2 * w2 + 1;

    // --- zero pads ---
    if (w2 == 0) {  // x=0 column of this output row: ii[y+1][0][c0..c0+31]
        g_ii[((size_t)(y + 1) * IIW) * FM_C + c0 + l] = 0.0f;
    }
    if (y == 0) {   // y=0 plane: ii[0][x][c] for all x
        for (int idx = threadIdx.x; idx < IIW * 32; idx += 512) {
            const int x = idx >> 5;
            const int c = idx & 31;
            g_ii[(size_t)x * FM_C + c0 + c] = 0.0f;
        }
    }

    const float4* srcA = (const float4*)(fm + (size_t)(c0 + cA) * (FM_H * FM_W)
                                            + (size_t)y * FM_W);
    const float4* srcB = (const float4*)(fm + (size_t)(c0 + cB) * (FM_H * FM_W)
                                            + (size_t)y * FM_W);
    const float4 z = make_float4(0.f, 0.f, 0.f, 0.f);
    // Round A: x4 = l (x 0..127). Round B: x4 = 32+l, valid l<18 (x 128..199).
    float4 a0 = __ldcs(&srcA[l]);
    float4 b0 = (l < 18) ? __ldcs(&srcA[32 + l]) : z;
    float4 a1 = __ldcs(&srcB[l]);
    float4 b1 = (l < 18) ? __ldcs(&srcB[32 + l]) : z;

    // quad-local inclusive prefix
    a0.y += a0.x; a0.z += a0.y; a0.w += a0.z;
    b0.y += b0.x; b0.z += b0.y; b0.w += b0.z;
    a1.y += a1.x; a1.z += a1.y; a1.w += a1.z;
    b1.y += b1.x; b1.z += b1.y; b1.w += b1.z;

    // four warp scans with ILP
    float sa0 = a0.w, sb0 = b0.w, sa1 = a1.w, sb1 = b1.w;
    #pragma unroll
    for (int d = 1; d < 32; d <<= 1) {
        float t0 = __shfl_up_sync(0xFFFFFFFFu, sa0, d);
        float t1 = __shfl_up_sync(0xFFFFFFFFu, sb0, d);
        float t2 = __shfl_up_sync(0xFFFFFFFFu, sa1, d);
        float t3 = __shfl_up_sync(0xFFFFFFFFu, sb1, d);
        if (l >= d) { sa0 += t0; sb0 += t1; sa1 += t2; sb1 += t3; }
    }
    const float eA0 = sa0 - a0.w;
    const float eB0 = (sb0 - b0.w) + __shfl_sync(0xFFFFFFFFu, sa0, 31);
    const float eA1 = sa1 - a1.w;
    const float eB1 = (sb1 - b1.w) + __shfl_sync(0xFFFFFFFFu, sa1, 31);
    a0.x += eA0; a0.y += eA0; a0.z += eA0; a0.w += eA0;
    b0.x += eB0; b0.y += eB0; b0.z += eB0; b0.w += eB0;
    a1.x += eA1; a1.y += eA1; a1.z += eA1; a1.w += eA1;
    b1.x += eB1; b1.y += eB1; b1.z += eB1; b1.w += eB1;

    // swizzled float4 staging: channel row = 256 floats = 64 16B-blocks
    const int key = w2 >> 1;               // = (c>>2)&7 for both cA, cB
    float4* S4 = (float4*)sh;
    S4[cA * 64 + (l ^ key)] = a0;
    S4[cB * 64 + (l ^ key)] = a1;
    if (l < 18) {
        S4[cA * 64 + ((32 + l) ^ key)] = b0;
        S4[cB * 64 + ((32 + l) ^ key)] = b1;
    }
    __syncthreads();

    // read 4 channels per thread (swizzle key = cq), float4 STG
    // 200 xi x 8 cq = 1600 pairs over 512 threads
    float* dstrow = g_ii + ((size_t)(y + 1) * IIW) * FM_C;
    #pragma unroll
    for (int idx = threadIdx.x; idx < 1600; idx += 512) {
        const int xi = idx >> 3;           // 0..199
        const int cq = idx & 7;
        const int base = (((xi >> 2) ^ cq) << 2) + (xi & 3);
        float4 o;
        o.x = sh[(4 * cq + 0) * 256 + base];
        o.y = sh[(4 * cq + 1) * 256 + base];
        o.z = sh[(4 * cq + 2) * 256 + base];
        o.w = sh[(4 * cq + 3) * 256 + base];
        ((float4*)(dstrow + (size_t)(xi + 1) * FM_C + c0))[cq] = o;
    }
}

// ---------------------------------------------------------------------------
// K2: y-cumsum in-place, channel-last. 400 blocks (200 x-columns x 2
// c-halves), 128 threads. Double-buffered 25-wide batches (8 iterations).
// ---------------------------------------------------------------------------
#define K2B 25
#define K2NB (FM_H / K2B)    // 8
__global__ void __launch_bounds__(128) k2_ycum() {
    const int x = blockIdx.x + 1;                    // 1..200
    const int c = blockIdx.y * 128 + threadIdx.x;    // 0..255
    float* col = g_ii + (size_t)x * FM_C + c;
    const size_t ystride = (size_t)IIW * FM_C;

    float va[K2B], vb[K2B];
    #pragma unroll
    for (int j = 0; j < K2B; j++) va[j] = col[(size_t)(1 + j) * ystride];

    float acc = 0.0f;
    #pragma unroll 1
    for (int i = 0; i < K2NB; i++) {
        if (i + 1 < K2NB) {
            const int yb = 1 + (i + 1) * K2B;
            #pragma unroll
            for (int j = 0; j < K2B; j++) vb[j] = col[(size_t)(yb + j) * ystride];
        }
        const int y0_ = 1 + i * K2B;
        #pragma unroll
        for (int j = 0; j < K2B; j++) {
            acc += va[j];
            col[(size_t)(y0_ + j) * ystride] = acc;
        }
        #pragma unroll
        for (int j = 0; j < K2B; j++) va[j] = vb[j];
    }
}

// ---------------------------------------------------------------------------
// K3: gather. One block per box (1024 blocks; 25.6KB smem -> 8 blocks/SM,
// capacity 1184 so still a single wave, with 2x block-level latency hiding).
// warp lanes = 8 channel-groups x 4 bins; S_PAD=25 conflict-free staging.
// Output stores evict-first (.cs) so streaming writes don't evict ii from L2.
// ---------------------------------------------------------------------------
#define S_PAD 25

template <int NB, int BIN0>
__device__ __forceinline__ void gather_pass(const float4* __restrict__ ii4,
                                            const int* __restrict__ soff,
                                            const float* __restrict__ srarea,
                                            float* __restrict__ sh,
                                            float* __restrict__ outn,
                                            int tid) {
    const int warp = tid >> 5;
    const int lane = tid & 31;
    const int cg = warp * 8 + (lane & 7);   // 0..63 channel group (float4)
    const int bsl = lane >> 3;              // 0..3 bin slot

    #pragma unroll
    for (int bb = bsl; bb < NB; bb += 4) {
        const int b = BIN0 + bb;
        const int o0 = soff[b * 4 + 0];
        const int o1 = soff[b * 4 + 1];
        const int o2 = soff[b * 4 + 2];
        const int o3 = soff[b * 4 + 3];
        const float4 A = ii4[o0 + cg];
        const float4 B = ii4[o1 + cg];
        const float4 C = ii4[o2 + cg];
        const float4 D = ii4[o3 + cg];
        const float ra = srarea[b];
        const int cb = cg * 4;
        sh[(cb + 0) * S_PAD + bb] = (A.x - B.x - C.x + D.x) * ra;
        sh[(cb + 1) * S_PAD + bb] = (A.y - B.y - C.y + D.y) * ra;
        sh[(cb + 2) * S_PAD + bb] = (A.z - B.z - C.z + D.z) * ra;
        sh[(cb + 3) * S_PAD + bb] = (A.w - B.w - C.w + D.w) * ra;
    }
    __syncthreads();
    #pragma unroll 4
    for (int idx = tid; idx < FM_C * NB; idx += 256) {
        const int c = idx / NB;               // NB constexpr -> magic multiply
        const int b = idx - c * NB;
        __stcs(&outn[c * NBINS + BIN0 + b], sh[c * S_PAD + b]);
    }
    __syncthreads();
}

__global__ void __launch_bounds__(256) k3_gather(const float* __restrict__ boxes,
                                                 float* __restrict__ out) {
    __shared__ float sh[FM_C * S_PAD];       // 25.6 KB
    __shared__ int   soff[NBINS * 4];
    __shared__ float srarea[NBINS];
    const int n = blockIdx.x;
    const int tid = threadIdx.x;

    if (tid < NBINS) {
        const float bx1 = __ldg(&boxes[n * 4 + 0]);
        const float by1 = __ldg(&boxes[n * 4 + 1]);
        const float bx2 = __ldg(&boxes[n * 4 + 2]);
        const float by2 = __ldg(&boxes[n * 4 + 3]);

        // scale = 200/800 = 0.25 exactly (bit-exact with reference)
        const int b0 = (int)floorf(bx1 * 0.25f);
        const int b1 = (int)floorf(by1 * 0.25f);
        const int b2 = (int)floorf(bx2 * 0.25f);
        const int b3 = (int)floorf(by2 * 0.25f);

        const int x1 = min(max(b0, 0), FM_W - 1);
        const int y1 = min(max(b1, 0), FM_H - 1);
        const int x2 = min(max(b2 + 1, x1 + 1), FM_W);
        const int y2 = min(max(b3 + 1, y1 + 1), FM_H);
        const int rh = y2 - y1;
        const int rw = x2 - x1;

        const int i = tid / OW;
        const int j = tid - i * OW;
        const int rs_ = y1 + (i * rh) / OH;
        const int re_ = y1 + ((i + 1) * rh + OH - 1) / OH;
        const int cs_ = x1 + (j * rw) / OW;
        const int ce_ = x1 + ((j + 1) * rw + OW - 1) / OW;

        soff[tid * 4 + 0] = (re_ * IIW + ce_) * (FM_C / 4);
        soff[tid * 4 + 1] = (rs_ * IIW + ce_) * (FM_C / 4);
        soff[tid * 4 + 2] = (re_ * IIW + cs_) * (FM_C / 4);
        soff[tid * 4 + 3] = (rs_ * IIW + cs_) * (FM_C / 4);
        srarea[tid] = 1.0f / (float)((re_ - rs_) * (ce_ - cs_));
    }
    __syncthreads();

    const float4* ii4 = (const float4*)g_ii;
    float* outn = out + (size_t)n * (FM_C * NBINS);

    gather_pass<25, 0>(ii4, soff, srarea, sh, outn, tid);
    gather_pass<24, 25>(ii4, soff, srarea, sh, outn, tid);
}

// ---------------------------------------------------------------------------
extern "C" void kernel_launch(void* const* d_in, const int* in_sizes, int n_in,
                              void* d_out, int out_size) {
    const float* fm    = (const float*)d_in[0];   // [1,256,200,200] fp32
    const float* boxes = (const float*)d_in[1];   // [1024,4] fp32
    float* out = (float*)d_out;                   // [1024,256,7,7] fp32

    {
        dim3 grid(FM_C / 32, FM_H);                  // (8, 200) = 1600 blocks
        k1_xcum_transpose<<<grid, 512>>>(fm);
    }
    {
        dim3 grid(FM_H, 2);                          // 400 blocks
        k2_ycum<<<grid, 128>>>();
    }
    k3_gather<<<NBOX, 256>>>(boxes, out);
}

// round 12
// speedup vs baseline: 1.0413x; 1.0413x over previous
#include <cuda_runtime.h>
#include <math.h>

#define FM_C 256
#define FM_H 200
#define FM_W 200
#define IIH 201
#define IIW 201
#define NBOX 1024
#define OH 7
#define OW 7
#define NBINS 49

// Integral image scratch, channel-last layout: [y][x][c], y,x in 0..200.
// After k1: ii[y+1][x+1][c] = x-cumsum of fm row y. After k2: full 2D cumsum.
__device__ float g_ii[IIH * IIW * FM_C];      // 41.4 MB

// ---------------------------------------------------------------------------
// K1: x-cumsum fused with transpose [C][H][W] -> [y+1][x+1][C].
// Grid (8 c-tiles, 200 rows), 512 threads (16 warps); each warp owns TWO
// channels (4-way scan ILP), 4 blocks/SM. float4 loads, quad-prefix + warp
// scans, float4 STS into XOR-swizzled [c][256] staging, float4 STG.
// ---------------------------------------------------------------------------
__global__ void __launch_bounds__(512) k1_xcum_transpose(const float* __restrict__ fm) {
    __shared__ float sh[32 * 256];         // 32 KB
    const int w2 = threadIdx.x >> 5;       // warp 0..15 -> channels 2w2, 2w2+1
    const int l = threadIdx.x & 31;
    const int c0 = blockIdx.x * 32;
    const int y  = blockIdx.y;             // fm row 0..199
    const int cA = 2 * w2;
    const int cB = 2 * w2 + 1;

    // --- zero pads ---
    if (w2 == 0) {  // x=0 column of this output row: ii[y+1][0][c0..c0+31]
        g_ii[((size_t)(y + 1) * IIW) * FM_C + c0 + l] = 0.0f;
    }
    if (y == 0) {   // y=0 plane: ii[0][x][c] for all x
        for (int idx = threadIdx.x; idx < IIW * 32; idx += 512) {
            const int x = idx >> 5;
            const int c = idx & 31;
            g_ii[(size_t)x * FM_C + c0 + c] = 0.0f;
        }
    }

    const float4* srcA = (const float4*)(fm + (size_t)(c0 + cA) * (FM_H * FM_W)
                                            + (size_t)y * FM_W);
    const float4* srcB = (const float4*)(fm + (size_t)(c0 + cB) * (FM_H * FM_W)
                                            + (size_t)y * FM_W);
    const float4 z = make_float4(0.f, 0.f, 0.f, 0.f);
    // Round A: x4 = l (x 0..127). Round B: x4 = 32+l, valid l<18 (x 128..199).
    float4 a0 = __ldcs(&srcA[l]);
    float4 b0 = (l < 18) ? __ldcs(&srcA[32 + l]) : z;
    float4 a1 = __ldcs(&srcB[l]);
    float4 b1 = (l < 18) ? __ldcs(&srcB[32 + l]) : z;

    // quad-local inclusive prefix
    a0.y += a0.x; a0.z += a0.y; a0.w += a0.z;
    b0.y += b0.x; b0.z += b0.y; b0.w += b0.z;
    a1.y += a1.x; a1.z += a1.y; a1.w += a1.z;
    b1.y += b1.x; b1.z += b1.y; b1.w += b1.z;

    // four warp scans with ILP
    float sa0 = a0.w, sb0 = b0.w, sa1 = a1.w, sb1 = b1.w;
    #pragma unroll
    for (int d = 1; d < 32; d <<= 1) {
        float t0 = __shfl_up_sync(0xFFFFFFFFu, sa0, d);
        float t1 = __shfl_up_sync(0xFFFFFFFFu, sb0, d);
        float t2 = __shfl_up_sync(0xFFFFFFFFu, sa1, d);
        float t3 = __shfl_up_sync(0xFFFFFFFFu, sb1, d);
        if (l >= d) { sa0 += t0; sb0 += t1; sa1 += t2; sb1 += t3; }
    }
    const float eA0 = sa0 - a0.w;
    const float eB0 = (sb0 - b0.w) + __shfl_sync(0xFFFFFFFFu, sa0, 31);
    const float eA1 = sa1 - a1.w;
    const float eB1 = (sb1 - b1.w) + __shfl_sync(0xFFFFFFFFu, sa1, 31);
    a0.x += eA0; a0.y += eA0; a0.z += eA0; a0.w += eA0;
    b0.x += eB0; b0.y += eB0; b0.z += eB0; b0.w += eB0;
    a1.x += eA1; a1.y += eA1; a1.z += eA1; a1.w += eA1;
    b1.x += eB1; b1.y += eB1; b1.z += eB1; b1.w += eB1;

    // swizzled float4 staging: channel row = 256 floats = 64 16B-blocks
    const int key = w2 >> 1;               // = (c>>2)&7 for both cA, cB
    float4* S4 = (float4*)sh;
    S4[cA * 64 + (l ^ key)] = a0;
    S4[cB * 64 + (l ^ key)] = a1;
    if (l < 18) {
        S4[cA * 64 + ((32 + l) ^ key)] = b0;
        S4[cB * 64 + ((32 + l) ^ key)] = b1;
    }
    __syncthreads();

    // read 4 channels per thread (swizzle key = cq), float4 STG
    // 200 xi x 8 cq = 1600 pairs over 512 threads
    float* dstrow = g_ii + ((size_t)(y + 1) * IIW) * FM_C;
    #pragma unroll
    for (int idx = threadIdx.x; idx < 1600; idx += 512) {
        const int xi = idx >> 3;           // 0..199
        const int cq = idx & 7;
        const int base = (((xi >> 2) ^ cq) << 2) + (xi & 3);
        float4 o;
        o.x = sh[(4 * cq + 0) * 256 + base];
        o.y = sh[(4 * cq + 1) * 256 + base];
        o.z = sh[(4 * cq + 2) * 256 + base];
        o.w = sh[(4 * cq + 3) * 256 + base];
        ((float4*)(dstrow + (size_t)(xi + 1) * FM_C + c0))[cq] = o;
    }
}

// ---------------------------------------------------------------------------
// K2: y-cumsum in-place, channel-last. 400 blocks (200 x-columns x 2
// c-halves), 128 threads. Double-buffered 20-wide batches (proven config;
// 25-wide caused register-pressure regression).
// ---------------------------------------------------------------------------
#define K2B 20
#define K2NB (FM_H / K2B)    // 10
__global__ void __launch_bounds__(128) k2_ycum() {
    const int x = blockIdx.x + 1;                    // 1..200
    const int c = blockIdx.y * 128 + threadIdx.x;    // 0..255
    float* col = g_ii + (size_t)x * FM_C + c;
    const size_t ystride = (size_t)IIW * FM_C;

    float va[K2B], vb[K2B];
    #pragma unroll
    for (int j = 0; j < K2B; j++) va[j] = col[(size_t)(1 + j) * ystride];

    float acc = 0.0f;
    #pragma unroll 1
    for (int i = 0; i < K2NB; i++) {
        if (i + 1 < K2NB) {
            const int yb = 1 + (i + 1) * K2B;
            #pragma unroll
            for (int j = 0; j < K2B; j++) vb[j] = col[(size_t)(yb + j) * ystride];
        }
        const int y0_ = 1 + i * K2B;
        #pragma unroll
        for (int j = 0; j < K2B; j++) {
            acc += va[j];
            col[(size_t)(y0_ + j) * ystride] = acc;
        }
        #pragma unroll
        for (int j = 0; j < K2B; j++) va[j] = vb[j];
    }
}

// ---------------------------------------------------------------------------
// K3: gather. One block per box (1024 blocks; 25.6KB smem -> 8 blocks/SM,
// ~7 resident blocks/SM vs ~3.5 at 512 blocks: grid-limited occupancy fix).
// warp lanes = 8 channel-groups x 4 bins; S_PAD=25 conflict-free staging.
// Output stores evict-first (.cs) so streaming writes don't evict ii from L2.
// ---------------------------------------------------------------------------
#define S_PAD 25

template <int NB, int BIN0>
__device__ __forceinline__ void gather_pass(const float4* __restrict__ ii4,
                                            const int* __restrict__ soff,
                                            const float* __restrict__ srarea,
                                            float* __restrict__ sh,
                                            float* __restrict__ outn,
                                            int tid) {
    const int warp = tid >> 5;
    const int lane = tid & 31;
    const int cg = warp * 8 + (lane & 7);   // 0..63 channel group (float4)
    const int bsl = lane >> 3;              // 0..3 bin slot

    #pragma unroll
    for (int bb = bsl; bb < NB; bb += 4) {
        const int b = BIN0 + bb;
        const int o0 = soff[b * 4 + 0];
        const int o1 = soff[b * 4 + 1];
        const int o2 = soff[b * 4 + 2];
        const int o3 = soff[b * 4 + 3];
        const float4 A = ii4[o0 + cg];
        const float4 B = ii4[o1 + cg];
        const float4 C = ii4[o2 + cg];
        const float4 D = ii4[o3 + cg];
        const float ra = srarea[b];
        const int cb = cg * 4;
        sh[(cb + 0) * S_PAD + bb] = (A.x - B.x - C.x + D.x) * ra;
        sh[(cb + 1) * S_PAD + bb] = (A.y - B.y - C.y + D.y) * ra;
        sh[(cb + 2) * S_PAD + bb] = (A.z - B.z - C.z + D.z) * ra;
        sh[(cb + 3) * S_PAD + bb] = (A.w - B.w - C.w + D.w) * ra;
    }
    __syncthreads();
    #pragma unroll 4
    for (int idx = tid; idx < FM_C * NB; idx += 256) {
        const int c = idx / NB;               // NB constexpr -> magic multiply
        const int b = idx - c * NB;
        __stcs(&outn[c * NBINS + BIN0 + b], sh[c * S_PAD + b]);
    }
    __syncthreads();
}

__global__ void __launch_bounds__(256) k3_gather(const float* __restrict__ boxes,
                                                 float* __restrict__ out) {
    __shared__ float sh[FM_C * S_PAD];       // 25.6 KB
    __shared__ int   soff[NBINS * 4];
    __shared__ float srarea[NBINS];
    const int n = blockIdx.x;
    const int tid = threadIdx.x;

    if (tid < NBINS) {
        const float bx1 = __ldg(&boxes[n * 4 + 0]);
        const float by1 = __ldg(&boxes[n * 4 + 1]);
        const float bx2 = __ldg(&boxes[n * 4 + 2]);
        const float by2 = __ldg(&boxes[n * 4 + 3]);

        // scale = 200/800 = 0.25 exactly (bit-exact with reference)
        const int b0 = (int)floorf(bx1 * 0.25f);
        const int b1 = (int)floorf(by1 * 0.25f);
        const int b2 = (int)floorf(bx2 * 0.25f);
        const int b3 = (int)floorf(by2 * 0.25f);

        const int x1 = min(max(b0, 0), FM_W - 1);
        const int y1 = min(max(b1, 0), FM_H - 1);
        const int x2 = min(max(b2 + 1, x1 + 1), FM_W);
        const int y2 = min(max(b3 + 1, y1 + 1), FM_H);
        const int rh = y2 - y1;
        const int rw = x2 - x1;

        const int i = tid / OW;
        const int j = tid - i * OW;
        const int rs_ = y1 + (i * rh) / OH;
        const int re_ = y1 + ((i + 1) * rh + OH - 1) / OH;
        const int cs_ = x1 + (j * rw) / OW;
        const int ce_ = x1 + ((j + 1) * rw + OW - 1) / OW;

        soff[tid * 4 + 0] = (re_ * IIW + ce_) * (FM_C / 4);
        soff[tid * 4 + 1] = (rs_ * IIW + ce_) * (FM_C / 4);
        soff[tid * 4 + 2] = (re_ * IIW + cs_) * (FM_C / 4);
        soff[tid * 4 + 3] = (rs_ * IIW + cs_) * (FM_C / 4);
        srarea[tid] = 1.0f / (float)((re_ - rs_) * (ce_ - cs_));
    }
    __syncthreads();

    const float4* ii4 = (const float4*)g_ii;
    float* outn = out + (size_t)n * (FM_C * NBINS);

    gather_pass<25, 0>(ii4, soff, srarea, sh, outn, tid);
    gather_pass<24, 25>(ii4, soff, srarea, sh, outn, tid);
}

// ---------------------------------------------------------------------------
extern "C" void kernel_launch(void* const* d_in, const int* in_sizes, int n_in,
                              void* d_out, int out_size) {
    const float* fm    = (const float*)d_in[0];   // [1,256,200,200] fp32
    const float* boxes = (const float*)d_in[1];   // [1024,4] fp32
    float* out = (float*)d_out;                   // [1024,256,7,7] fp32

    {
        dim3 grid(FM_C / 32, FM_H);                  // (8, 200) = 1600 blocks
        k1_xcum_transpose<<<grid, 512>>>(fm);
    }
    {
        dim3 grid(FM_H, 2);                          // 400 blocks
        k2_ycum<<<grid, 128>>>();
    }
    k3_gather<<<NBOX, 256>>>(boxes, out);
}